// round 4
// baseline (speedup 1.0000x reference)
#include <cuda_runtime.h>
#include <math.h>

#define Nn   10000
#define Ee   160000
#define Aa   8
#define EMBc 128
#define D1   512
#define NFc  1500
#define OUTC 64

// ---------------- device scratch (static, no allocation) ----------------
__device__ float g_pemb[Nn*EMBc];
__device__ float g_xl1[Nn*D1];
__device__ float g_xr1[Nn*D1];
__device__ float g_h  [Nn*D1];
__device__ float g_xl2[Nn*D1];
__device__ float g_xr2[Nn*D1];
__device__ float g_hiA[Aa*Nn*D1];
__device__ float g_attW1[64*D1];
__device__ float g_attW2[64*D1];
__device__ float g_eeloop1[D1];
__device__ float g_eeloop2[Aa*D1];
__device__ int   g_deg[Nn];
__device__ int   g_fill[Nn];
__device__ int   g_rowptr[Nn+1];
__device__ int   g_csr_val[Ee];   // src | (attr<<16)
__device__ int   g_csr_eid[Ee];
__device__ unsigned g_maskA[Nn];
__device__ unsigned g_maskB[Nn];
__device__ int   g_cnt1[64];
__device__ int   g_cnt[Aa*64];
__device__ float g_frame_x[D1];
__device__ float g_role_x[Aa*D1];
__device__ float g_outf[OUTC];
__device__ float g_outr[Aa*OUTC];

// ---------------- small helpers ----------------
__device__ __forceinline__ float geluf(float x){
    return 0.5f*x*(1.0f+erff(x*0.70710678118654752440f));
}
__device__ __forceinline__ float lrelu(float x){ return x > 0.f ? x : 0.2f*x; }

// ---------------- zero scratch (capture-safe, replaces cudaMemsetAsync) ----------------
__global__ void k_zero(){
    int i = blockIdx.x*blockDim.x + threadIdx.x;
    if (i < Nn){ g_deg[i]=0; g_fill[i]=0; g_maskA[i]=0u; }
    if (i < 64) g_cnt1[i]=0;
    if (i < Aa*64) g_cnt[i]=0;
}

__global__ void k_copymask(const unsigned* __restrict__ s, unsigned* __restrict__ d){
    int i = blockIdx.x*blockDim.x + threadIdx.x;
    if (i < Nn) d[i]=s[i];
}

// ---------------- gather node predicate embeddings ----------------
__global__ void k_gpemb(const int* __restrict__ np, const float* __restrict__ pe){
    int i = blockIdx.x*blockDim.x + threadIdx.x;
    if (i >= Nn*32) return;
    int n = i >> 5, c4 = i & 31;
    ((float4*)g_pemb)[n*32 + c4] = ((const float4*)pe)[(size_t)np[n]*32 + c4];
}

// ---------------- generic fp32 GEMM: C[M,Nl] = A[M,K] @ B[K,Nl] ----------------
// 128x128 tile, BK=16, 256 threads, 8x8 microtile
__global__ __launch_bounds__(256) void k_gemm(float* __restrict__ C,
                                              const float* __restrict__ A,
                                              const float* __restrict__ B,
                                              int M, int Nl, int K){
    __shared__ float As[16][128];
    __shared__ float Bs[16][128];
    int bx = blockIdx.x, by = blockIdx.y;
    int tid = threadIdx.x;
    int tx = tid & 15, ty = tid >> 4;
    int row0 = by*128 + ty*8;
    int col0 = bx*128 + tx*8;
    float acc[8][8];
    #pragma unroll
    for (int i=0;i<8;i++)
        #pragma unroll
        for (int j=0;j<8;j++) acc[i][j]=0.f;

    for (int k0=0;k0<K;k0+=16){
        {   // load A tile (transposed into As[k][r])
            int r = tid >> 1, h = (tid & 1)*8;
            int gr = by*128 + r;
            float4 v0 = make_float4(0,0,0,0), v1 = v0;
            if (gr < M){
                const float* ap = A + (size_t)gr*K + k0 + h;
                v0 = *(const float4*)ap;
                v1 = *(const float4*)(ap+4);
            }
            As[h+0][r]=v0.x; As[h+1][r]=v0.y; As[h+2][r]=v0.z; As[h+3][r]=v0.w;
            As[h+4][r]=v1.x; As[h+5][r]=v1.y; As[h+6][r]=v1.z; As[h+7][r]=v1.w;
        }
        {   // load B tile
            int kk = tid >> 4, c = (tid & 15)*8;
            int gc = bx*128 + c;
            float4 w0 = make_float4(0,0,0,0), w1 = w0;
            if (gc < Nl){
                const float* bp = B + (size_t)(k0+kk)*Nl + gc;
                w0 = *(const float4*)bp;
                w1 = *(const float4*)(bp+4);
            }
            *(float4*)&Bs[kk][c]   = w0;
            *(float4*)&Bs[kk][c+4] = w1;
        }
        __syncthreads();
        #pragma unroll
        for (int k=0;k<16;k++){
            float a[8], b[8];
            *(float4*)(a  ) = *(float4*)&As[k][ty*8];
            *(float4*)(a+4) = *(float4*)&As[k][ty*8+4];
            *(float4*)(b  ) = *(float4*)&Bs[k][tx*8];
            *(float4*)(b+4) = *(float4*)&Bs[k][tx*8+4];
            #pragma unroll
            for (int i=0;i<8;i++)
                #pragma unroll
                for (int j=0;j<8;j++) acc[i][j] += a[i]*b[j];
        }
        __syncthreads();
    }
    if (col0 < Nl){
        #pragma unroll
        for (int i=0;i<8;i++){
            int gr = row0 + i;
            if (gr < M){
                float* cp = C + (size_t)gr*Nl + col0;
                *(float4*)(cp  ) = make_float4(acc[i][0],acc[i][1],acc[i][2],acc[i][3]);
                *(float4*)(cp+4) = make_float4(acc[i][4],acc[i][5],acc[i][6],acc[i][7]);
            }
        }
    }
}

// ---------------- attr histogram over all edges ----------------
__global__ void k_cnt1k(const int* __restrict__ attr){
    __shared__ int h[64];
    if (threadIdx.x < 64) h[threadIdx.x]=0;
    __syncthreads();
    for (int e = blockIdx.x*blockDim.x+threadIdx.x; e < Ee; e += gridDim.x*blockDim.x)
        atomicAdd(&h[attr[e]], 1);
    __syncthreads();
    if (threadIdx.x < 64) atomicAdd(&g_cnt1[threadIdx.x], h[threadIdx.x]);
}

__global__ void k_eeloop1k(){
    int d = threadIdx.x; // 512
    float s = 0.f;
    for (int t=0;t<64;t++) s += (float)g_cnt1[t]*g_attW1[t*D1+d];
    g_eeloop1[d] = s/(float)Ee;
}

// ---------------- CSR build (by dst) ----------------
__global__ void k_degk(const int* __restrict__ dstA){
    for (int e = blockIdx.x*blockDim.x+threadIdx.x; e < Ee; e += gridDim.x*blockDim.x)
        atomicAdd(&g_deg[dstA[e]], 1);
}

__global__ __launch_bounds__(1024) void k_scan(){
    __shared__ int sh[1024];
    __shared__ int off;
    int t = threadIdx.x;
    if (t==0) off = 0;
    __syncthreads();
    for (int base=0; base<Nn; base+=1024){
        int v = (base+t < Nn) ? g_deg[base+t] : 0;
        sh[t]=v; __syncthreads();
        for (int o=1;o<1024;o<<=1){
            int addv = (t>=o) ? sh[t-o] : 0;
            __syncthreads();
            sh[t] += addv;
            __syncthreads();
        }
        if (base+t < Nn) g_rowptr[base+t] = off + sh[t] - v;
        __syncthreads();
        if (t==1023) off += sh[1023];
        __syncthreads();
    }
    if (t==0) g_rowptr[Nn] = off;
}

__global__ void k_scatterk(const int* __restrict__ srcA, const int* __restrict__ dstA,
                           const int* __restrict__ attr){
    for (int e = blockIdx.x*blockDim.x+threadIdx.x; e < Ee; e += gridDim.x*blockDim.x){
        int d = dstA[e];
        int pos = atomicAdd(&g_fill[d], 1);
        int idx = g_rowptr[d] + pos;
        g_csr_val[idx] = srcA[e] | (attr[e]<<16);
        g_csr_eid[idx] = e;
    }
}

// deterministic order: insertion sort each dst segment by original edge id
__global__ void k_sortseg(){
    int n = blockIdx.x*blockDim.x + threadIdx.x;
    if (n >= Nn) return;
    int b = g_rowptr[n], e = g_rowptr[n+1];
    for (int i=b+1;i<e;i++){
        int ke = g_csr_eid[i], kv = g_csr_val[i];
        int j = i-1;
        while (j>=b && g_csr_eid[j] > ke){
            g_csr_eid[j+1]=g_csr_eid[j]; g_csr_val[j+1]=g_csr_val[j]; j--;
        }
        g_csr_eid[j+1]=ke; g_csr_val[j+1]=kv;
    }
}

// ---------------- k-hop masks (8 args as bit fields) ----------------
__global__ void k_maskinit(const int* __restrict__ argn, unsigned* __restrict__ mA){
    int a = threadIdx.x;
    if (a < Aa) atomicOr(&mA[argn[a]], 1u<<a);
}

__global__ void k_hopk(const int* __restrict__ srcA, const int* __restrict__ dstA,
                       const unsigned* __restrict__ mo, unsigned* __restrict__ mn2){
    for (int e = blockIdx.x*blockDim.x+threadIdx.x; e < Ee; e += gridDim.x*blockDim.x){
        unsigned b = mo[dstA[e]];
        if (b) atomicOr(&mn2[srcA[e]], b);
    }
}

// ---------------- kept-edge attr counts per arg ----------------
__global__ void k_cntkept(const int* __restrict__ srcA, const int* __restrict__ dstA,
                          const int* __restrict__ attr, const unsigned* __restrict__ maskp){
    __shared__ int h[Aa*64];
    for (int i=threadIdx.x;i<Aa*64;i+=blockDim.x) h[i]=0;
    __syncthreads();
    for (int e = blockIdx.x*blockDim.x+threadIdx.x; e < Ee; e += gridDim.x*blockDim.x){
        unsigned bits = maskp[srcA[e]] & maskp[dstA[e]];
        int at = attr[e];
        while (bits){
            int a = __ffs(bits)-1;
            bits &= bits-1u;
            atomicAdd(&h[a*64+at], 1);
        }
    }
    __syncthreads();
    for (int i=threadIdx.x;i<Aa*64;i+=blockDim.x) atomicAdd(&g_cnt[i], h[i]);
}

__global__ void k_eeloop2k(){
    int a = blockIdx.x, d = threadIdx.x; // 8 x 512
    float s = 0.f; int tot = 0;
    for (int t=0;t<64;t++){
        int c = g_cnt[a*64+t];
        tot += c;
        s += (float)c * g_attW2[t*D1+d];
    }
    g_eeloop2[a*D1+d] = s/(float)(tot>1?tot:1);
}

// ---------------- GATv2 full-graph pass ----------------
// warp w == head w; lane l covers 4 contiguous channels d = 4l..4l+3 of head w
// -> all tensor loads are float4, head score reduced via shfl_xor. No block syncs.
__global__ __launch_bounds__(128) void k_gat1(const float* __restrict__ xl,
                                              const float* __restrict__ xr,
                                              const float* __restrict__ att,
                                              const float* __restrict__ bias,
                                              const float* __restrict__ eeloop,
                                              const float* __restrict__ attW,
                                              float* __restrict__ outp){
    int dst = blockIdx.x;
    int w = threadIdx.x >> 5, l = threadIdx.x & 31;
    int c4 = w*32 + l;                      // float4 index into a 512-f row
    const float4* xl4  = (const float4*)xl;
    float4 attv = ((const float4*)att)[c4];
    float4 xrv  = ((const float4*)xr)[(size_t)dst*128 + c4];
    float4 acc  = make_float4(0.f,0.f,0.f,0.f);
    float mh = -INFINITY, lh = 0.f;
    int beg = g_rowptr[dst], end = g_rowptr[dst+1];
    for (int i = beg-1; i < end; ++i){
        int srcn; const float4* eep;
        if (i < beg){ srcn = dst; eep = (const float4*)eeloop; }
        else { int pv = g_csr_val[i]; srcn = pv & 0xFFFF; eep = (const float4*)attW + (size_t)(pv>>16)*128; }
        float4 xv = xl4[(size_t)srcn*128 + c4];
        float4 ee = eep[c4];
        float p = lrelu(xv.x+xrv.x+ee.x)*attv.x + lrelu(xv.y+xrv.y+ee.y)*attv.y
                + lrelu(xv.z+xrv.z+ee.z)*attv.z + lrelu(xv.w+xrv.w+ee.w)*attv.w;
        #pragma unroll
        for (int o=16;o;o>>=1) p += __shfl_xor_sync(0xffffffffu, p, o);
        float mn = fmaxf(mh, p);
        float c  = __expf(mh - mn);
        float pe = __expf(p  - mn);
        lh = lh*c + pe; mh = mn;
        acc.x = acc.x*c + pe*xv.x; acc.y = acc.y*c + pe*xv.y;
        acc.z = acc.z*c + pe*xv.z; acc.w = acc.w*c + pe*xv.w;
    }
    float inv = 1.f/(lh + 1e-16f);
    float4 bv = ((const float4*)bias)[c4];
    float4 ov = make_float4(acc.x*inv+bv.x, acc.y*inv+bv.y, acc.z*inv+bv.z, acc.w*inv+bv.w);
    ((float4*)outp)[(size_t)dst*128 + c4] = ov;
}

// ---------------- fused 8-arg masked GATv2 pass ----------------
// One edge visit serves every arg whose bit is in mask[src]&mask[dst]:
// the attention score is mask-independent; only the online-softmax
// accumulator set differs per arg.
__global__ __launch_bounds__(128) void k_gat8(const float* __restrict__ xl,
                                              const float* __restrict__ xr,
                                              const float* __restrict__ att,
                                              const float* __restrict__ bias,
                                              const float* __restrict__ eel2,
                                              const float* __restrict__ attW,
                                              float* __restrict__ outp,
                                              const unsigned* __restrict__ mask){
    int dst = blockIdx.x;
    unsigned mdst = mask[dst];
    if (!mdst) return;
    int w = threadIdx.x >> 5, l = threadIdx.x & 31;
    int c4 = w*32 + l;
    const float4* xl4 = (const float4*)xl;
    float4 attv = ((const float4*)att)[c4];
    float4 xrv  = ((const float4*)xr)[(size_t)dst*128 + c4];
    float4 xld  = xl4[(size_t)dst*128 + c4];
    float mh[Aa], lh[Aa];
    float4 acc[Aa];
    #pragma unroll
    for (int a=0;a<Aa;a++){
        mh[a] = -INFINITY; lh[a] = 0.f;
        acc[a] = make_float4(0.f,0.f,0.f,0.f);
    }
    // self-loops (per-arg mean-edge attr)
    #pragma unroll
    for (int a=0;a<Aa;a++){
        if (!((mdst>>a)&1u)) continue;
        float4 ee = ((const float4*)eel2)[a*128 + c4];
        float p = lrelu(xld.x+xrv.x+ee.x)*attv.x + lrelu(xld.y+xrv.y+ee.y)*attv.y
                + lrelu(xld.z+xrv.z+ee.z)*attv.z + lrelu(xld.w+xrv.w+ee.w)*attv.w;
        #pragma unroll
        for (int o=16;o;o>>=1) p += __shfl_xor_sync(0xffffffffu, p, o);
        mh[a] = p; lh[a] = 1.f;
        acc[a] = xld;
    }
    // shared edge walk
    int beg = g_rowptr[dst], end = g_rowptr[dst+1];
    for (int i = beg; i < end; ++i){
        int pv = g_csr_val[i];
        int srcn = pv & 0xFFFF;
        unsigned eb = mdst & mask[srcn];
        if (!eb) continue;
        float4 xv = xl4[(size_t)srcn*128 + c4];
        float4 ee = ((const float4*)attW)[(size_t)(pv>>16)*128 + c4];
        float p = lrelu(xv.x+xrv.x+ee.x)*attv.x + lrelu(xv.y+xrv.y+ee.y)*attv.y
                + lrelu(xv.z+xrv.z+ee.z)*attv.z + lrelu(xv.w+xrv.w+ee.w)*attv.w;
        #pragma unroll
        for (int o=16;o;o>>=1) p += __shfl_xor_sync(0xffffffffu, p, o);
        #pragma unroll
        for (int a=0;a<Aa;a++){
            if (!((eb>>a)&1u)) continue;
            float mn = fmaxf(mh[a], p);
            float c  = __expf(mh[a] - mn);
            float pe = __expf(p - mn);
            lh[a] = lh[a]*c + pe; mh[a] = mn;
            acc[a].x = acc[a].x*c + pe*xv.x; acc[a].y = acc[a].y*c + pe*xv.y;
            acc[a].z = acc[a].z*c + pe*xv.z; acc[a].w = acc[a].w*c + pe*xv.w;
        }
    }
    float4 bv = ((const float4*)bias)[c4];
    #pragma unroll
    for (int a=0;a<Aa;a++){
        if (!((mdst>>a)&1u)) continue;
        float inv = 1.f/(lh[a] + 1e-16f);
        float4 ov = make_float4(acc[a].x*inv+bv.x, acc[a].y*inv+bv.y,
                                acc[a].z*inv+bv.z, acc[a].w*inv+bv.w);
        ((float4*)outp)[(size_t)a*Nn*128 + (size_t)dst*128 + c4] = ov;
    }
}

// ---------------- per-channel softmax aggregation over nodes ----------------
// block handles 32 channels; 512 threads (16 warps); two-pass (max, then sum)
__device__ __forceinline__ void smaggr_body(const float* __restrict__ x,
                                            const unsigned* __restrict__ maskp,
                                            unsigned bit,
                                            float* __restrict__ outv, int d0){
    int lane = threadIdx.x & 31, w = threadIdx.x >> 5;  // 16 warps
    int d = d0 + lane;
    __shared__ float sm[16][32];
    __shared__ float sl[16][32];
    __shared__ float ssv[16][32];

    float m = -INFINITY;
    for (int n=w; n<Nn; n+=16){
        if (maskp && !(maskp[n]&bit)) continue;
        m = fmaxf(m, x[(size_t)n*D1 + d]);
    }
    sm[w][lane]=m; __syncthreads();
    float M = sm[0][lane];
    #pragma unroll
    for (int k=1;k<16;k++) M = fmaxf(M, sm[k][lane]);
    __syncthreads();

    float l=0.f, s=0.f;
    for (int n=w; n<Nn; n+=16){
        if (maskp && !(maskp[n]&bit)) continue;
        float v = x[(size_t)n*D1 + d];
        float e = __expf(v - M);
        l += e; s += e*v;
    }
    sl[w][lane]=l; ssv[w][lane]=s; __syncthreads();
    if (w==0){
        float L=0.f, S=0.f;
        #pragma unroll
        for (int k=0;k<16;k++){ L += sl[k][lane]; S += ssv[k][lane]; }
        outv[d] = S/(L + 1e-30f);
    }
}

__global__ __launch_bounds__(512) void k_smaggr_full(const float* __restrict__ x,
                                                     float* __restrict__ outv){
    smaggr_body(x, (const unsigned*)0, 0u, outv, blockIdx.x*32);
}

__global__ __launch_bounds__(512) void k_smaggr8(const float* __restrict__ xbase,
                                                 const unsigned* __restrict__ maskp,
                                                 float* __restrict__ outbase){
    int a = blockIdx.y;
    smaggr_body(xbase + (size_t)a*Nn*D1, maskp, 1u<<a,
                outbase + (size_t)a*D1, blockIdx.x*32);
}

// ---------------- HGT + tiny heads ----------------
__global__ __launch_bounds__(512) void k_head(const float* __restrict__ kqv_f, const float* __restrict__ kqvb_f,
                                              const float* __restrict__ kqv_r, const float* __restrict__ kqvb_r,
                                              const float* __restrict__ a_rel, const float* __restrict__ m_rel,
                                              const float* __restrict__ p_rel,
                                              const float* __restrict__ aW_f, const float* __restrict__ ab_f,
                                              const float* __restrict__ aW_r, const float* __restrict__ ab_r){
    __shared__ float kf[64], vf[64];
    __shared__ float kr[Aa][64], qr[Aa][64], vr[Aa][64];
    __shared__ float kra[Aa][64], vrm[Aa][64];
    __shared__ float kfa[64], vfm1[64], aggf[64];
    __shared__ float aggr[Aa][64];
    __shared__ float sfr[Aa], srr[Aa];
    int t = threadIdx.x;       // 512
    int a = t >> 6, o = t & 63;

    // phase 1: kr/qr/vr (all), kf/vf (t<64)
    {
        float accK = kqvb_r[o], accQ = kqvb_r[64+o], accV = kqvb_r[128+o];
        const float* rx = g_role_x + (size_t)a*D1;
        for (int k=0;k<D1;k++){
            float x = rx[k];
            accK += x*kqv_r[(size_t)(        k)*64+o];
            accQ += x*kqv_r[(size_t)(  D1 + k)*64+o];
            accV += x*kqv_r[(size_t)(2*D1 + k)*64+o];
        }
        kr[a][o]=accK; qr[a][o]=accQ; vr[a][o]=accV;
    }
    if (t < 64){
        float aK = kqvb_f[o], aV = kqvb_f[128+o];
        for (int k=0;k<D1;k++){
            float x = g_frame_x[k];
            aK += x*kqv_f[(size_t)k*64+o];
            aV += x*kqv_f[(size_t)(2*D1+k)*64+o];
        }
        kf[o]=aK; vf[o]=aV;
    }
    __syncthreads();

    // phase 2
    if (t < 64){
        float s1=0.f, s0=0.f, s2=0.f;
        for (int k=0;k<64;k++){
            s1 += kf[k]*a_rel[(64 + k)*64 + o];
            s0 += vf[k]*m_rel[(     k)*64 + o];
            s2 += vf[k]*m_rel[(64 + k)*64 + o];
        }
        kfa[o]=s1; aggf[o]=s0; vfm1[o]=s2;
    }
    {
        float kv=0.f, vv=0.f;
        for (int k=0;k<64;k++){
            kv += kr[a][k]*a_rel[(128 + k)*64 + o];
            vv += vr[a][k]*m_rel[(128 + k)*64 + o];
        }
        kra[a][o]=kv; vrm[a][o]=vv;
    }
    __syncthreads();

    // phase 3: attention over {frame->role, role self-loop}
    if (t < Aa){
        const float sq = 0.125f;
        float f=0.f, r=0.f;
        for (int k=0;k<64;k++){ f += qr[t][k]*kfa[k]; r += qr[t][k]*kra[t][k]; }
        f *= sq*p_rel[1]; r *= sq*p_rel[2];
        float mx = fmaxf(f,r);
        float ef = expf(f-mx), er = expf(r-mx);
        float inv = 1.f/(ef+er);
        sfr[t]=ef*inv; srr[t]=er*inv;
    }
    __syncthreads();

    aggr[a][o] = sfr[a]*vfm1[o] + srr[a]*vrm[a][o];
    __syncthreads();

    if (t < 64){
        float s = ab_f[o];
        for (int k=0;k<64;k++) s += geluf(aggf[k])*aW_f[k*64+o];
        g_outf[o] = s;
    }
    {
        float s = ab_r[o];
        for (int k=0;k<64;k++) s += geluf(aggr[a][k])*aW_r[k*64+o];
        g_outr[a*64+o] = s;
    }
}

__global__ __launch_bounds__(512) void k_frame(const float* __restrict__ Wfr,
                                               const float* __restrict__ bfr,
                                               float* __restrict__ outp){
    __shared__ float sf[64];
    __shared__ float lg[NFc];
    __shared__ float red[512];
    int t = threadIdx.x;
    if (t < 64) sf[t] = g_outf[t];
    __syncthreads();
    for (int i=t;i<NFc;i+=512){
        float s = bfr[i];
        for (int k=0;k<64;k++) s += sf[k]*Wfr[(size_t)k*NFc+i];
        lg[i]=s;
    }
    __syncthreads();
    float m = -INFINITY;
    for (int i=t;i<NFc;i+=512) m = fmaxf(m, lg[i]);
    red[t]=m; __syncthreads();
    for (int o=256;o;o>>=1){ if(t<o) red[t]=fmaxf(red[t],red[t+o]); __syncthreads(); }
    m = red[0]; __syncthreads();
    float s = 0.f;
    for (int i=t;i<NFc;i+=512) s += expf(lg[i]-m);
    red[t]=s; __syncthreads();
    for (int o=256;o;o>>=1){ if(t<o) red[t]+=red[t+o]; __syncthreads(); }
    float lse = logf(red[0]);
    for (int i=t;i<NFc;i+=512) outp[i] = lg[i]-m-lse;
}

__global__ __launch_bounds__(512) void k_roles(const float* __restrict__ Wro,
                                               const float* __restrict__ bro,
                                               float* __restrict__ outp){
    __shared__ float lg[Aa][64];
    __shared__ float rm[Aa], rs[Aa];
    int t = threadIdx.x;
    int a = t >> 6, o = t & 63;
    float s = bro[o];
    for (int k=0;k<64;k++) s += g_outr[a*64+k]*Wro[k*64+o];
    lg[a][o]=s;
    __syncthreads();
    if (o==0){
        float m=-INFINITY;
        for (int k=0;k<64;k++) m = fmaxf(m, lg[a][k]);
        float sm=0.f;
        for (int k=0;k<64;k++) sm += expf(lg[a][k]-m);
        rm[a]=m; rs[a]=logf(sm);
    }
    __syncthreads();
    outp[a*64+o] = lg[a][o]-rm[a]-rs[a];
}

// ---------------- host launcher ----------------
extern "C" void kernel_launch(void* const* d_in, const int* in_sizes, int n_in,
                              void* d_out, int out_size){
    const int*   node_pred = (const int*)d_in[0];
    const int*   edge_index= (const int*)d_in[1];
    const int*   edge_attr = (const int*)d_in[2];
    const int*   arg_nodes = (const int*)d_in[3];
    const float* pred_emb  = (const float*)d_in[4];
    const float* Wl1=(const float*)d_in[5], *Wr1=(const float*)d_in[6], *We1=(const float*)d_in[7];
    const float* att1=(const float*)d_in[8], *b1=(const float*)d_in[9];
    const float* Wl2=(const float*)d_in[10], *Wr2=(const float*)d_in[11], *We2=(const float*)d_in[12];
    const float* att2=(const float*)d_in[13], *b2=(const float*)d_in[14];
    const float* kqv_f=(const float*)d_in[15], *kqvb_f=(const float*)d_in[16];
    const float* kqv_r=(const float*)d_in[17], *kqvb_r=(const float*)d_in[18];
    const float* a_rel=(const float*)d_in[19], *m_rel=(const float*)d_in[20], *p_rel=(const float*)d_in[21];
    const float* aW_f=(const float*)d_in[22], *ab_f=(const float*)d_in[23];
    const float* aW_r=(const float*)d_in[24], *ab_r=(const float*)d_in[25];
    const float* Wfr=(const float*)d_in[26], *bfr=(const float*)d_in[27];
    const float* Wro=(const float*)d_in[28], *bro=(const float*)d_in[29];
    float* outp = (float*)d_out;

    const int* srcA = edge_index;
    const int* dstA = edge_index + Ee;

    void *p_pemb,*p_xl1,*p_xr1,*p_h,*p_xl2,*p_xr2,*p_hiA,*p_attW1,*p_attW2;
    void *p_ee1,*p_ee2,*p_mA,*p_mB,*p_fx,*p_rx;
    cudaGetSymbolAddress(&p_pemb,  g_pemb);
    cudaGetSymbolAddress(&p_xl1,   g_xl1);
    cudaGetSymbolAddress(&p_xr1,   g_xr1);
    cudaGetSymbolAddress(&p_h,     g_h);
    cudaGetSymbolAddress(&p_xl2,   g_xl2);
    cudaGetSymbolAddress(&p_xr2,   g_xr2);
    cudaGetSymbolAddress(&p_hiA,   g_hiA);
    cudaGetSymbolAddress(&p_attW1, g_attW1);
    cudaGetSymbolAddress(&p_attW2, g_attW2);
    cudaGetSymbolAddress(&p_ee1,   g_eeloop1);
    cudaGetSymbolAddress(&p_ee2,   g_eeloop2);
    cudaGetSymbolAddress(&p_mA,    g_maskA);
    cudaGetSymbolAddress(&p_mB,    g_maskB);
    cudaGetSymbolAddress(&p_fx,    g_frame_x);
    cudaGetSymbolAddress(&p_rx,    g_role_x);

    // zero scratch (kernel, not cudaMemsetAsync — capture-safe)
    k_zero<<<(Nn+255)/256, 256>>>();

    // gather p_emb
    k_gpemb<<<(Nn*32+255)/256, 256>>>(node_pred, pred_emb);

    // attr embedding tables (only 64 distinct attrs; a_emb = pred_emb[attr])
    {
        dim3 g((D1+127)/128, 1);
        k_gemm<<<g, 256>>>((float*)p_attW1, pred_emb, We1, 64, D1, EMBc);
        k_gemm<<<g, 256>>>((float*)p_attW2, pred_emb, We2, 64, D1, EMBc);
    }
    // xl1/xr1
    {
        dim3 g((D1+127)/128, (Nn+127)/128);
        k_gemm<<<g, 256>>>((float*)p_xl1, (const float*)p_pemb, Wl1, Nn, D1, EMBc);
        k_gemm<<<g, 256>>>((float*)p_xr1, (const float*)p_pemb, Wr1, Nn, D1, EMBc);
    }

    // mean-edge self-loop term for layer 1
    k_cnt1k<<<128, 256>>>(edge_attr);
    k_eeloop1k<<<1, 512>>>();

    // CSR by dst (deterministic: segments sorted by original edge id)
    k_degk<<<(Ee+255)/256, 256>>>(dstA);
    k_scan<<<1, 1024>>>();
    k_scatterk<<<(Ee+255)/256, 256>>>(srcA, dstA, edge_attr);
    k_sortseg<<<(Nn+127)/128, 128>>>();

    // k-hop masks (3 hops, ping-pong A/B via copy kernels, final in B)
    k_maskinit<<<1, 32>>>(arg_nodes, (unsigned*)p_mA);
    k_copymask<<<(Nn+255)/256, 256>>>((const unsigned*)p_mA, (unsigned*)p_mB);
    k_hopk<<<(Ee+255)/256, 256>>>(srcA, dstA, (const unsigned*)p_mA, (unsigned*)p_mB);
    k_copymask<<<(Nn+255)/256, 256>>>((const unsigned*)p_mB, (unsigned*)p_mA);
    k_hopk<<<(Ee+255)/256, 256>>>(srcA, dstA, (const unsigned*)p_mB, (unsigned*)p_mA);
    k_copymask<<<(Nn+255)/256, 256>>>((const unsigned*)p_mA, (unsigned*)p_mB);
    k_hopk<<<(Ee+255)/256, 256>>>(srcA, dstA, (const unsigned*)p_mA, (unsigned*)p_mB);

    // GAT layer 1 (full graph) -> h
    k_gat1<<<Nn, 128>>>((const float*)p_xl1, (const float*)p_xr1, att1, b1,
                        (const float*)p_ee1, (const float*)p_attW1, (float*)p_h);
    k_smaggr_full<<<D1/32, 512>>>((const float*)p_h, (float*)p_fx);

    // xl2/xr2 (shared across all args)
    {
        dim3 g((D1+127)/128, (Nn+127)/128);
        k_gemm<<<g, 256>>>((float*)p_xl2, (const float*)p_h, Wl2, Nn, D1, D1);
        k_gemm<<<g, 256>>>((float*)p_xr2, (const float*)p_h, Wr2, Nn, D1, D1);
    }

    // per-arg kept-edge attr counts -> self-loop terms
    k_cntkept<<<128, 256>>>(srcA, dstA, edge_attr, (const unsigned*)p_mB);
    k_eeloop2k<<<Aa, 512>>>();

    // fused 8-arg masked GAT + per-arg softmax aggregation
    k_gat8<<<Nn, 128>>>((const float*)p_xl2, (const float*)p_xr2, att2, b2,
                        (const float*)p_ee2, (const float*)p_attW2,
                        (float*)p_hiA, (const unsigned*)p_mB);
    {
        dim3 g(D1/32, Aa);
        k_smaggr8<<<g, 512>>>((const float*)p_hiA, (const unsigned*)p_mB, (float*)p_rx);
    }

    // HGT + heads
    k_head<<<1, 512>>>(kqv_f, kqvb_f, kqv_r, kqvb_r, a_rel, m_rel, p_rel,
                       aW_f, ab_f, aW_r, ab_r);
    k_frame<<<1, 512>>>(Wfr, bfr, outp);
    k_roles<<<1, 512>>>(Wro, bro, outp + NFc);
}

// round 7
// speedup vs baseline: 1.1418x; 1.1418x over previous
#include <cuda_runtime.h>
#include <math.h>

#define Nn   10000
#define Ee   160000
#define Aa   8
#define EMBc 128
#define D1   512
#define NFc  1500
#define OUTC 64

// ---------------- device scratch (static, no allocation) ----------------
__device__ float g_pemb[Nn*EMBc];
__device__ float g_xl1[Nn*D1];
__device__ float g_xr1[Nn*D1];
__device__ float g_h  [Nn*D1];
__device__ float g_xl2[Nn*D1];
__device__ float g_xr2[Nn*D1];
__device__ float g_hiA[Aa*Nn*D1];
__device__ float g_attW1[64*D1];
__device__ float g_attW2[64*D1];
__device__ float g_eeloop1[D1];
__device__ float g_eeloop2[Aa*D1];
__device__ int   g_deg[Nn];
__device__ int   g_fill[Nn];
__device__ int   g_rowptr[Nn+1];
__device__ int   g_csr_val[Ee];   // src | (attr<<16)
__device__ int   g_csr_eid[Ee];
__device__ unsigned g_maskA[Nn];
__device__ unsigned g_maskB[Nn];
__device__ int   g_cnt1[64];
__device__ int   g_cnt[Aa*64];
__device__ float g_frame_x[D1];
__device__ float g_role_x[Aa*D1];
__device__ float g_outf[OUTC];
__device__ float g_outr[Aa*OUTC];

// ---------------- small helpers ----------------
__device__ __forceinline__ float geluf(float x){
    return 0.5f*x*(1.0f+erff(x*0.70710678118654752440f));
}
__device__ __forceinline__ float lrelu(float x){ return x > 0.f ? x : 0.2f*x; }

__device__ __forceinline__ unsigned f2tf32(float x){
    unsigned r; asm("cvt.rna.tf32.f32 %0, %1;\n" : "=r"(r) : "f"(x)); return r;
}
__device__ __forceinline__ void mma_tf32(float* c, const unsigned* a, const unsigned* b){
    asm volatile("mma.sync.aligned.m16n8k8.row.col.f32.tf32.tf32.f32 "
        "{%0,%1,%2,%3}, {%4,%5,%6,%7}, {%8,%9}, {%0,%1,%2,%3};\n"
        : "+f"(c[0]), "+f"(c[1]), "+f"(c[2]), "+f"(c[3])
        : "r"(a[0]), "r"(a[1]), "r"(a[2]), "r"(a[3]), "r"(b[0]), "r"(b[1]));
}

// ---------------- zero scratch (capture-safe) ----------------
__global__ void k_zero(){
    int i = blockIdx.x*blockDim.x + threadIdx.x;
    if (i < Nn){ g_deg[i]=0; g_fill[i]=0; g_maskA[i]=0u; }
    if (i < 64) g_cnt1[i]=0;
    if (i < Aa*64) g_cnt[i]=0;
}

__global__ void k_copymask(const unsigned* __restrict__ s, unsigned* __restrict__ d){
    int i = blockIdx.x*blockDim.x + threadIdx.x;
    if (i < Nn) d[i]=s[i];
}

// ---------------- gather node predicate embeddings ----------------
__global__ void k_gpemb(const int* __restrict__ np, const float* __restrict__ pe){
    int i = blockIdx.x*blockDim.x + threadIdx.x;
    if (i >= Nn*32) return;
    int n = i >> 5, c4 = i & 31;
    ((float4*)g_pemb)[n*32 + c4] = ((const float4*)pe)[(size_t)np[n]*32 + c4];
}

// ---------------- 3xTF32 tensor-core GEMM: C[M,Nl] = A[M,K] @ B[K,Nl] ----------------
// 128x64 CTA tile, BK=16, 256 threads (8 warps, 4x2 warp grid, 32x32 warp tile).
// Full fp32 accuracy via big/residual tf32 split (3 mmas per tile).
__global__ __launch_bounds__(256) void k_gemm_tf32(float* __restrict__ C,
                                                   const float* __restrict__ A,
                                                   const float* __restrict__ B,
                                                   int M, int Nl, int K){
    __shared__ float As[128][20];
    __shared__ float Bs[16][72];
    int tid = threadIdx.x;
    int lane = tid & 31, wid = tid >> 5;
    int wm = (wid & 3)*32, wn = (wid >> 2)*32;
    int g = lane >> 2, t4 = lane & 3;
    int bx = blockIdx.x, by = blockIdx.y;
    float acc[2][4][4];
    #pragma unroll
    for (int i=0;i<2;i++)
        #pragma unroll
        for (int j=0;j<4;j++)
            #pragma unroll
            for (int q=0;q<4;q++) acc[i][j][q]=0.f;

    for (int k0=0;k0<K;k0+=16){
        // A tile 128x16 (512 float4, 2 per thread)
        #pragma unroll
        for (int i=0;i<2;i++){
            int idx = tid*2 + i;
            int row = idx >> 2, c4 = idx & 3;
            float4 v = make_float4(0,0,0,0);
            int gr = by*128 + row;
            if (gr < M) v = *(const float4*)(A + (size_t)gr*K + k0 + c4*4);
            As[row][c4*4+0]=v.x; As[row][c4*4+1]=v.y;
            As[row][c4*4+2]=v.z; As[row][c4*4+3]=v.w;
        }
        // B tile 16x64 (256 float4, 1 per thread)
        {
            int row = tid >> 4, c4 = tid & 15;
            float4 v = make_float4(0,0,0,0);
            int gc = bx*64 + c4*4;
            if (gc < Nl) v = *(const float4*)(B + (size_t)(k0+row)*Nl + gc);
            Bs[row][c4*4+0]=v.x; Bs[row][c4*4+1]=v.y;
            Bs[row][c4*4+2]=v.z; Bs[row][c4*4+3]=v.w;
        }
        __syncthreads();
        #pragma unroll
        for (int ks=0; ks<16; ks+=8){
            unsigned ab[2][4], ar[2][4];
            #pragma unroll
            for (int mf=0; mf<2; mf++){
                float a0 = As[wm+mf*16+g  ][ks+t4  ];
                float a1 = As[wm+mf*16+g+8][ks+t4  ];
                float a2 = As[wm+mf*16+g  ][ks+t4+4];
                float a3 = As[wm+mf*16+g+8][ks+t4+4];
                ab[mf][0]=f2tf32(a0); ar[mf][0]=f2tf32(a0-__uint_as_float(ab[mf][0]));
                ab[mf][1]=f2tf32(a1); ar[mf][1]=f2tf32(a1-__uint_as_float(ab[mf][1]));
                ab[mf][2]=f2tf32(a2); ar[mf][2]=f2tf32(a2-__uint_as_float(ab[mf][2]));
                ab[mf][3]=f2tf32(a3); ar[mf][3]=f2tf32(a3-__uint_as_float(ab[mf][3]));
            }
            unsigned bb[4][2], br[4][2];
            #pragma unroll
            for (int nf=0; nf<4; nf++){
                float b0 = Bs[ks+t4  ][wn+nf*8+g];
                float b1 = Bs[ks+t4+4][wn+nf*8+g];
                bb[nf][0]=f2tf32(b0); br[nf][0]=f2tf32(b0-__uint_as_float(bb[nf][0]));
                bb[nf][1]=f2tf32(b1); br[nf][1]=f2tf32(b1-__uint_as_float(bb[nf][1]));
            }
            #pragma unroll
            for (int mf=0;mf<2;mf++)
                #pragma unroll
                for (int nf=0;nf<4;nf++){
                    mma_tf32(acc[mf][nf], ab[mf], bb[nf]);
                    mma_tf32(acc[mf][nf], ab[mf], br[nf]);
                    mma_tf32(acc[mf][nf], ar[mf], bb[nf]);
                }
        }
        __syncthreads();
    }
    #pragma unroll
    for (int mf=0;mf<2;mf++){
        #pragma unroll
        for (int nf=0;nf<4;nf++){
            int col = bx*64 + wn + nf*8 + 2*t4;
            int r0 = by*128 + wm + mf*16 + g;
            if (r0 < M && col < Nl){
                C[(size_t)r0*Nl + col]   = acc[mf][nf][0];
                C[(size_t)r0*Nl + col+1] = acc[mf][nf][1];
            }
            int r1 = r0 + 8;
            if (r1 < M && col < Nl){
                C[(size_t)r1*Nl + col]   = acc[mf][nf][2];
                C[(size_t)r1*Nl + col+1] = acc[mf][nf][3];
            }
        }
    }
}

// ---------------- attr histogram over all edges ----------------
__global__ void k_cnt1k(const int* __restrict__ attr){
    __shared__ int h[64];
    if (threadIdx.x < 64) h[threadIdx.x]=0;
    __syncthreads();
    for (int e = blockIdx.x*blockDim.x+threadIdx.x; e < Ee; e += gridDim.x*blockDim.x)
        atomicAdd(&h[attr[e]], 1);
    __syncthreads();
    if (threadIdx.x < 64) atomicAdd(&g_cnt1[threadIdx.x], h[threadIdx.x]);
}

__global__ void k_eeloop1k(){
    int d = threadIdx.x; // 512
    float s = 0.f;
    for (int t=0;t<64;t++) s += (float)g_cnt1[t]*g_attW1[t*D1+d];
    g_eeloop1[d] = s/(float)Ee;
}

// ---------------- CSR build (by dst) ----------------
__global__ void k_degk(const int* __restrict__ dstA){
    for (int e = blockIdx.x*blockDim.x+threadIdx.x; e < Ee; e += gridDim.x*blockDim.x)
        atomicAdd(&g_deg[dstA[e]], 1);
}

// register-chunk + warp-shuffle exclusive scan of g_deg -> g_rowptr (2 barriers)
__global__ __launch_bounds__(1024) void k_scan(){
    __shared__ int wsum[32];
    int t = threadIdx.x;
    const int CH = 10;                 // 1024*10 >= Nn
    int base = t*CH;
    int v[CH]; int s=0;
    #pragma unroll
    for (int i=0;i<CH;i++){
        int idx = base+i;
        int d = (idx<Nn)? g_deg[idx] : 0;
        v[i] = s; s += d;
    }
    int lane = t&31, w = t>>5;
    int inc = s;
    #pragma unroll
    for (int o=1;o<32;o<<=1){
        int n = __shfl_up_sync(0xffffffffu, inc, o);
        if (lane>=o) inc += n;
    }
    if (lane==31) wsum[w]=inc;
    __syncthreads();
    if (w==0){
        int x = wsum[lane];
        #pragma unroll
        for (int o=1;o<32;o<<=1){
            int n = __shfl_up_sync(0xffffffffu, x, o);
            if (lane>=o) x += n;
        }
        wsum[lane]=x;
    }
    __syncthreads();
    int offset = inc - s + (w>0 ? wsum[w-1] : 0);
    #pragma unroll
    for (int i=0;i<CH;i++){
        int idx = base+i;
        if (idx<Nn) g_rowptr[idx] = offset + v[i];
    }
    if (t==1023) g_rowptr[Nn] = offset + s;
}

__global__ void k_scatterk(const int* __restrict__ srcA, const int* __restrict__ dstA,
                           const int* __restrict__ attr){
    for (int e = blockIdx.x*blockDim.x+threadIdx.x; e < Ee; e += gridDim.x*blockDim.x){
        int d = dstA[e];
        int pos = atomicAdd(&g_fill[d], 1);
        int idx = g_rowptr[d] + pos;
        g_csr_val[idx] = srcA[e] | (attr[e]<<16);
        g_csr_eid[idx] = e;
    }
}

// deterministic order: insertion sort each dst segment by original edge id
__global__ void k_sortseg(){
    int n = blockIdx.x*blockDim.x + threadIdx.x;
    if (n >= Nn) return;
    int b = g_rowptr[n], e = g_rowptr[n+1];
    for (int i=b+1;i<e;i++){
        int ke = g_csr_eid[i], kv = g_csr_val[i];
        int j = i-1;
        while (j>=b && g_csr_eid[j] > ke){
            g_csr_eid[j+1]=g_csr_eid[j]; g_csr_val[j+1]=g_csr_val[j]; j--;
        }
        g_csr_eid[j+1]=ke; g_csr_val[j+1]=kv;
    }
}

// ---------------- k-hop masks (8 args as bit fields) ----------------
__global__ void k_maskinit(const int* __restrict__ argn, unsigned* __restrict__ mA){
    int a = threadIdx.x;
    if (a < Aa) atomicOr(&mA[argn[a]], 1u<<a);
}

__global__ void k_hopk(const int* __restrict__ srcA, const int* __restrict__ dstA,
                       const unsigned* __restrict__ mo, unsigned* __restrict__ mn2){
    for (int e = blockIdx.x*blockDim.x+threadIdx.x; e < Ee; e += gridDim.x*blockDim.x){
        unsigned b = mo[dstA[e]];
        if (b) atomicOr(&mn2[srcA[e]], b);
    }
}

// ---------------- kept-edge attr counts per arg ----------------
__global__ void k_cntkept(const int* __restrict__ srcA, const int* __restrict__ dstA,
                          const int* __restrict__ attr, const unsigned* __restrict__ maskp){
    __shared__ int h[Aa*64];
    for (int i=threadIdx.x;i<Aa*64;i+=blockDim.x) h[i]=0;
    __syncthreads();
    for (int e = blockIdx.x*blockDim.x+threadIdx.x; e < Ee; e += gridDim.x*blockDim.x){
        unsigned bits = maskp[srcA[e]] & maskp[dstA[e]];
        int at = attr[e];
        while (bits){
            int a = __ffs(bits)-1;
            bits &= bits-1u;
            atomicAdd(&h[a*64+at], 1);
        }
    }
    __syncthreads();
    for (int i=threadIdx.x;i<Aa*64;i+=blockDim.x) atomicAdd(&g_cnt[i], h[i]);
}

__global__ void k_eeloop2k(){
    int a = blockIdx.x, d = threadIdx.x; // 8 x 512
    float s = 0.f; int tot = 0;
    for (int t=0;t<64;t++){
        int c = g_cnt[a*64+t];
        tot += c;
        s += (float)c * g_attW2[t*D1+d];
    }
    g_eeloop2[a*D1+d] = s/(float)(tot>1?tot:1);
}

// ---------------- GATv2 full-graph pass ----------------
// warp w == head w; lane l covers 4 contiguous channels d = 4l..4l+3 of head w
// -> all tensor loads are float4, head score reduced via shfl_xor. No block syncs.
__global__ __launch_bounds__(128) void k_gat1(const float* __restrict__ xl,
                                              const float* __restrict__ xr,
                                              const float* __restrict__ att,
                                              const float* __restrict__ bias,
                                              const float* __restrict__ eeloop,
                                              const float* __restrict__ attW,
                                              float* __restrict__ outp){
    int dst = blockIdx.x;
    int w = threadIdx.x >> 5, l = threadIdx.x & 31;
    int c4 = w*32 + l;                      // float4 index into a 512-f row
    const float4* xl4  = (const float4*)xl;
    float4 attv = ((const float4*)att)[c4];
    float4 xrv  = ((const float4*)xr)[(size_t)dst*128 + c4];
    float4 acc  = make_float4(0.f,0.f,0.f,0.f);
    float mh = -INFINITY, lh = 0.f;
    int beg = g_rowptr[dst], end = g_rowptr[dst+1];
    for (int i = beg-1; i < end; ++i){
        int srcn; const float4* eep;
        if (i < beg){ srcn = dst; eep = (const float4*)eeloop; }
        else { int pv = g_csr_val[i]; srcn = pv & 0xFFFF; eep = (const float4*)attW + (size_t)(pv>>16)*128; }
        float4 xv = xl4[(size_t)srcn*128 + c4];
        float4 ee = eep[c4];
        float p = lrelu(xv.x+xrv.x+ee.x)*attv.x + lrelu(xv.y+xrv.y+ee.y)*attv.y
                + lrelu(xv.z+xrv.z+ee.z)*attv.z + lrelu(xv.w+xrv.w+ee.w)*attv.w;
        #pragma unroll
        for (int o=16;o;o>>=1) p += __shfl_xor_sync(0xffffffffu, p, o);
        float mn = fmaxf(mh, p);
        float c  = __expf(mh - mn);
        float pe = __expf(p  - mn);
        lh = lh*c + pe; mh = mn;
        acc.x = acc.x*c + pe*xv.x; acc.y = acc.y*c + pe*xv.y;
        acc.z = acc.z*c + pe*xv.z; acc.w = acc.w*c + pe*xv.w;
    }
    float inv = 1.f/(lh + 1e-16f);
    float4 bv = ((const float4*)bias)[c4];
    float4 ov = make_float4(acc.x*inv+bv.x, acc.y*inv+bv.y, acc.z*inv+bv.z, acc.w*inv+bv.w);
    ((float4*)outp)[(size_t)dst*128 + c4] = ov;
}

// ---------------- fused 8-arg masked GATv2 pass ----------------
__global__ __launch_bounds__(128) void k_gat8(const float* __restrict__ xl,
                                              const float* __restrict__ xr,
                                              const float* __restrict__ att,
                                              const float* __restrict__ bias,
                                              const float* __restrict__ eel2,
                                              const float* __restrict__ attW,
                                              float* __restrict__ outp,
                                              const unsigned* __restrict__ mask){
    int dst = blockIdx.x;
    unsigned mdst = mask[dst];
    if (!mdst) return;
    int w = threadIdx.x >> 5, l = threadIdx.x & 31;
    int c4 = w*32 + l;
    const float4* xl4 = (const float4*)xl;
    float4 attv = ((const float4*)att)[c4];
    float4 xrv  = ((const float4*)xr)[(size_t)dst*128 + c4];
    float4 xld  = xl4[(size_t)dst*128 + c4];
    float mh[Aa], lh[Aa];
    float4 acc[Aa];
    #pragma unroll
    for (int a=0;a<Aa;a++){
        mh[a] = -INFINITY; lh[a] = 0.f;
        acc[a] = make_float4(0.f,0.f,0.f,0.f);
    }
    // self-loops (per-arg mean-edge attr)
    #pragma unroll
    for (int a=0;a<Aa;a++){
        if (!((mdst>>a)&1u)) continue;
        float4 ee = ((const float4*)eel2)[a*128 + c4];
        float p = lrelu(xld.x+xrv.x+ee.x)*attv.x + lrelu(xld.y+xrv.y+ee.y)*attv.y
                + lrelu(xld.z+xrv.z+ee.z)*attv.z + lrelu(xld.w+xrv.w+ee.w)*attv.w;
        #pragma unroll
        for (int o=16;o;o>>=1) p += __shfl_xor_sync(0xffffffffu, p, o);
        mh[a] = p; lh[a] = 1.f;
        acc[a] = xld;
    }
    // shared edge walk
    int beg = g_rowptr[dst], end = g_rowptr[dst+1];
    for (int i = beg; i < end; ++i){
        int pv = g_csr_val[i];
        int srcn = pv & 0xFFFF;
        unsigned eb = mdst & mask[srcn];
        if (!eb) continue;
        float4 xv = xl4[(size_t)srcn*128 + c4];
        float4 ee = ((const float4*)attW)[(size_t)(pv>>16)*128 + c4];
        float p = lrelu(xv.x+xrv.x+ee.x)*attv.x + lrelu(xv.y+xrv.y+ee.y)*attv.y
                + lrelu(xv.z+xrv.z+ee.z)*attv.z + lrelu(xv.w+xrv.w+ee.w)*attv.w;
        #pragma unroll
        for (int o=16;o;o>>=1) p += __shfl_xor_sync(0xffffffffu, p, o);
        #pragma unroll
        for (int a=0;a<Aa;a++){
            if (!((eb>>a)&1u)) continue;
            float mn = fmaxf(mh[a], p);
            float c  = __expf(mh[a] - mn);
            float pe = __expf(p - mn);
            lh[a] = lh[a]*c + pe; mh[a] = mn;
            acc[a].x = acc[a].x*c + pe*xv.x; acc[a].y = acc[a].y*c + pe*xv.y;
            acc[a].z = acc[a].z*c + pe*xv.z; acc[a].w = acc[a].w*c + pe*xv.w;
        }
    }
    float4 bv = ((const float4*)bias)[c4];
    #pragma unroll
    for (int a=0;a<Aa;a++){
        if (!((mdst>>a)&1u)) continue;
        float inv = 1.f/(lh[a] + 1e-16f);
        float4 ov = make_float4(acc[a].x*inv+bv.x, acc[a].y*inv+bv.y,
                                acc[a].z*inv+bv.z, acc[a].w*inv+bv.w);
        ((float4*)outp)[(size_t)a*Nn*128 + (size_t)dst*128 + c4] = ov;
    }
}

// ---------------- per-channel softmax aggregation over nodes ----------------
__device__ __forceinline__ void smaggr_body(const float* __restrict__ x,
                                            const unsigned* __restrict__ maskp,
                                            unsigned bit,
                                            float* __restrict__ outv, int d0){
    int lane = threadIdx.x & 31, w = threadIdx.x >> 5;  // 16 warps
    int d = d0 + lane;
    __shared__ float sm[16][32];
    __shared__ float sl[16][32];
    __shared__ float ssv[16][32];

    float m = -INFINITY;
    for (int n=w; n<Nn; n+=16){
        if (maskp && !(maskp[n]&bit)) continue;
        m = fmaxf(m, x[(size_t)n*D1 + d]);
    }
    sm[w][lane]=m; __syncthreads();
    float M = sm[0][lane];
    #pragma unroll
    for (int k=1;k<16;k++) M = fmaxf(M, sm[k][lane]);
    __syncthreads();

    float l=0.f, s=0.f;
    for (int n=w; n<Nn; n+=16){
        if (maskp && !(maskp[n]&bit)) continue;
        float v = x[(size_t)n*D1 + d];
        float e = __expf(v - M);
        l += e; s += e*v;
    }
    sl[w][lane]=l; ssv[w][lane]=s; __syncthreads();
    if (w==0){
        float L=0.f, S=0.f;
        #pragma unroll
        for (int k=0;k<16;k++){ L += sl[k][lane]; S += ssv[k][lane]; }
        outv[d] = S/(L + 1e-30f);
    }
}

__global__ __launch_bounds__(512) void k_smaggr_full(const float* __restrict__ x,
                                                     float* __restrict__ outv){
    smaggr_body(x, (const unsigned*)0, 0u, outv, blockIdx.x*32);
}

__global__ __launch_bounds__(512) void k_smaggr8(const float* __restrict__ xbase,
                                                 const unsigned* __restrict__ maskp,
                                                 float* __restrict__ outbase){
    int a = blockIdx.y;
    smaggr_body(xbase + (size_t)a*Nn*D1, maskp, 1u<<a,
                outbase + (size_t)a*D1, blockIdx.x*32);
}

// ---------------- HGT + tiny heads ----------------
__global__ __launch_bounds__(512) void k_head(const float* __restrict__ kqv_f, const float* __restrict__ kqvb_f,
                                              const float* __restrict__ kqv_r, const float* __restrict__ kqvb_r,
                                              const float* __restrict__ a_rel, const float* __restrict__ m_rel,
                                              const float* __restrict__ p_rel,
                                              const float* __restrict__ aW_f, const float* __restrict__ ab_f,
                                              const float* __restrict__ aW_r, const float* __restrict__ ab_r){
    __shared__ float kf[64], vf[64];
    __shared__ float kr[Aa][64], qr[Aa][64], vr[Aa][64];
    __shared__ float kra[Aa][64], vrm[Aa][64];
    __shared__ float kfa[64], vfm1[64], aggf[64];
    __shared__ float aggr[Aa][64];
    __shared__ float sfr[Aa], srr[Aa];
    int t = threadIdx.x;       // 512
    int a = t >> 6, o = t & 63;

    {
        float accK = kqvb_r[o], accQ = kqvb_r[64+o], accV = kqvb_r[128+o];
        const float* rx = g_role_x + (size_t)a*D1;
        for (int k=0;k<D1;k++){
            float x = rx[k];
            accK += x*kqv_r[(size_t)(        k)*64+o];
            accQ += x*kqv_r[(size_t)(  D1 + k)*64+o];
            accV += x*kqv_r[(size_t)(2*D1 + k)*64+o];
        }
        kr[a][o]=accK; qr[a][o]=accQ; vr[a][o]=accV;
    }
    if (t < 64){
        float aK = kqvb_f[o], aV = kqvb_f[128+o];
        for (int k=0;k<D1;k++){
            float x = g_frame_x[k];
            aK += x*kqv_f[(size_t)k*64+o];
            aV += x*kqv_f[(size_t)(2*D1+k)*64+o];
        }
        kf[o]=aK; vf[o]=aV;
    }
    __syncthreads();

    if (t < 64){
        float s1=0.f, s0=0.f, s2=0.f;
        for (int k=0;k<64;k++){
            s1 += kf[k]*a_rel[(64 + k)*64 + o];
            s0 += vf[k]*m_rel[(     k)*64 + o];
            s2 += vf[k]*m_rel[(64 + k)*64 + o];
        }
        kfa[o]=s1; aggf[o]=s0; vfm1[o]=s2;
    }
    {
        float kv=0.f, vv=0.f;
        for (int k=0;k<64;k++){
            kv += kr[a][k]*a_rel[(128 + k)*64 + o];
            vv += vr[a][k]*m_rel[(128 + k)*64 + o];
        }
        kra[a][o]=kv; vrm[a][o]=vv;
    }
    __syncthreads();

    if (t < Aa){
        const float sq = 0.125f;
        float f=0.f, r=0.f;
        for (int k=0;k<64;k++){ f += qr[t][k]*kfa[k]; r += qr[t][k]*kra[t][k]; }
        f *= sq*p_rel[1]; r *= sq*p_rel[2];
        float mx = fmaxf(f,r);
        float ef = expf(f-mx), er = expf(r-mx);
        float inv = 1.f/(ef+er);
        sfr[t]=ef*inv; srr[t]=er*inv;
    }
    __syncthreads();

    aggr[a][o] = sfr[a]*vfm1[o] + srr[a]*vrm[a][o];
    __syncthreads();

    if (t < 64){
        float s = ab_f[o];
        for (int k=0;k<64;k++) s += geluf(aggf[k])*aW_f[k*64+o];
        g_outf[o] = s;
    }
    {
        float s = ab_r[o];
        for (int k=0;k<64;k++) s += geluf(aggr[a][k])*aW_r[k*64+o];
        g_outr[a*64+o] = s;
    }
}

__global__ __launch_bounds__(512) void k_frame(const float* __restrict__ Wfr,
                                               const float* __restrict__ bfr,
                                               float* __restrict__ outp){
    __shared__ float sf[64];
    __shared__ float lg[NFc];
    __shared__ float red[512];
    int t = threadIdx.x;
    if (t < 64) sf[t] = g_outf[t];
    __syncthreads();
    for (int i=t;i<NFc;i+=512){
        float s = bfr[i];
        for (int k=0;k<64;k++) s += sf[k]*Wfr[(size_t)k*NFc+i];
        lg[i]=s;
    }
    __syncthreads();
    float m = -INFINITY;
    for (int i=t;i<NFc;i+=512) m = fmaxf(m, lg[i]);
    red[t]=m; __syncthreads();
    for (int o=256;o;o>>=1){ if(t<o) red[t]=fmaxf(red[t],red[t+o]); __syncthreads(); }
    m = red[0]; __syncthreads();
    float s = 0.f;
    for (int i=t;i<NFc;i+=512) s += expf(lg[i]-m);
    red[t]=s; __syncthreads();
    for (int o=256;o;o>>=1){ if(t<o) red[t]+=red[t+o]; __syncthreads(); }
    float lse = logf(red[0]);
    for (int i=t;i<NFc;i+=512) outp[i] = lg[i]-m-lse;
}

__global__ __launch_bounds__(512) void k_roles(const float* __restrict__ Wro,
                                               const float* __restrict__ bro,
                                               float* __restrict__ outp){
    __shared__ float lg[Aa][64];
    __shared__ float rm[Aa], rs[Aa];
    int t = threadIdx.x;
    int a = t >> 6, o = t & 63;
    float s = bro[o];
    for (int k=0;k<64;k++) s += g_outr[a*64+k]*Wro[k*64+o];
    lg[a][o]=s;
    __syncthreads();
    if (o==0){
        float m=-INFINITY;
        for (int k=0;k<64;k++) m = fmaxf(m, lg[a][k]);
        float sm=0.f;
        for (int k=0;k<64;k++) sm += expf(lg[a][k]-m);
        rm[a]=m; rs[a]=logf(sm);
    }
    __syncthreads();
    outp[a*64+o] = lg[a][o]-rm[a]-rs[a];
}

// ---------------- host launcher ----------------
extern "C" void kernel_launch(void* const* d_in, const int* in_sizes, int n_in,
                              void* d_out, int out_size){
    const int*   node_pred = (const int*)d_in[0];
    const int*   edge_index= (const int*)d_in[1];
    const int*   edge_attr = (const int*)d_in[2];
    const int*   arg_nodes = (const int*)d_in[3];
    const float* pred_emb  = (const float*)d_in[4];
    const float* Wl1=(const float*)d_in[5], *Wr1=(const float*)d_in[6], *We1=(const float*)d_in[7];
    const float* att1=(const float*)d_in[8], *b1=(const float*)d_in[9];
    const float* Wl2=(const float*)d_in[10], *Wr2=(const float*)d_in[11], *We2=(const float*)d_in[12];
    const float* att2=(const float*)d_in[13], *b2=(const float*)d_in[14];
    const float* kqv_f=(const float*)d_in[15], *kqvb_f=(const float*)d_in[16];
    const float* kqv_r=(const float*)d_in[17], *kqvb_r=(const float*)d_in[18];
    const float* a_rel=(const float*)d_in[19], *m_rel=(const float*)d_in[20], *p_rel=(const float*)d_in[21];
    const float* aW_f=(const float*)d_in[22], *ab_f=(const float*)d_in[23];
    const float* aW_r=(const float*)d_in[24], *ab_r=(const float*)d_in[25];
    const float* Wfr=(const float*)d_in[26], *bfr=(const float*)d_in[27];
    const float* Wro=(const float*)d_in[28], *bro=(const float*)d_in[29];
    float* outp = (float*)d_out;

    const int* srcA = edge_index;
    const int* dstA = edge_index + Ee;

    void *p_pemb,*p_xl1,*p_xr1,*p_h,*p_xl2,*p_xr2,*p_hiA,*p_attW1,*p_attW2;
    void *p_ee1,*p_ee2,*p_mA,*p_mB,*p_fx,*p_rx;
    cudaGetSymbolAddress(&p_pemb,  g_pemb);
    cudaGetSymbolAddress(&p_xl1,   g_xl1);
    cudaGetSymbolAddress(&p_xr1,   g_xr1);
    cudaGetSymbolAddress(&p_h,     g_h);
    cudaGetSymbolAddress(&p_xl2,   g_xl2);
    cudaGetSymbolAddress(&p_xr2,   g_xr2);
    cudaGetSymbolAddress(&p_hiA,   g_hiA);
    cudaGetSymbolAddress(&p_attW1, g_attW1);
    cudaGetSymbolAddress(&p_attW2, g_attW2);
    cudaGetSymbolAddress(&p_ee1,   g_eeloop1);
    cudaGetSymbolAddress(&p_ee2,   g_eeloop2);
    cudaGetSymbolAddress(&p_mA,    g_maskA);
    cudaGetSymbolAddress(&p_mB,    g_maskB);
    cudaGetSymbolAddress(&p_fx,    g_frame_x);
    cudaGetSymbolAddress(&p_rx,    g_role_x);

    // zero scratch (kernel, not cudaMemsetAsync — capture-safe)
    k_zero<<<(Nn+255)/256, 256>>>();

    // gather p_emb
    k_gpemb<<<(Nn*32+255)/256, 256>>>(node_pred, pred_emb);

    // attr embedding tables (only 64 distinct attrs; a_emb = pred_emb[attr])
    {
        dim3 g(D1/64, 1);
        k_gemm_tf32<<<g, 256>>>((float*)p_attW1, pred_emb, We1, 64, D1, EMBc);
        k_gemm_tf32<<<g, 256>>>((float*)p_attW2, pred_emb, We2, 64, D1, EMBc);
    }
    // xl1/xr1
    {
        dim3 g(D1/64, (Nn+127)/128);
        k_gemm_tf32<<<g, 256>>>((float*)p_xl1, (const float*)p_pemb, Wl1, Nn, D1, EMBc);
        k_gemm_tf32<<<g, 256>>>((float*)p_xr1, (const float*)p_pemb, Wr1, Nn, D1, EMBc);
    }

    // mean-edge self-loop term for layer 1
    k_cnt1k<<<128, 256>>>(edge_attr);
    k_eeloop1k<<<1, 512>>>();

    // CSR by dst (deterministic: segments sorted by original edge id)
    k_degk<<<(Ee+255)/256, 256>>>(dstA);
    k_scan<<<1, 1024>>>();
    k_scatterk<<<(Ee+255)/256, 256>>>(srcA, dstA, edge_attr);
    k_sortseg<<<(Nn+127)/128, 128>>>();

    // k-hop masks (3 hops, ping-pong A/B via copy kernels, final in B)
    k_maskinit<<<1, 32>>>(arg_nodes, (unsigned*)p_mA);
    k_copymask<<<(Nn+255)/256, 256>>>((const unsigned*)p_mA, (unsigned*)p_mB);
    k_hopk<<<(Ee+255)/256, 256>>>(srcA, dstA, (const unsigned*)p_mA, (unsigned*)p_mB);
    k_copymask<<<(Nn+255)/256, 256>>>((const unsigned*)p_mB, (unsigned*)p_mA);
    k_hopk<<<(Ee+255)/256, 256>>>(srcA, dstA, (const unsigned*)p_mB, (unsigned*)p_mA);
    k_copymask<<<(Nn+255)/256, 256>>>((const unsigned*)p_mA, (unsigned*)p_mB);
    k_hopk<<<(Ee+255)/256, 256>>>(srcA, dstA, (const unsigned*)p_mA, (unsigned*)p_mB);

    // GAT layer 1 (full graph) -> h
    k_gat1<<<Nn, 128>>>((const float*)p_xl1, (const float*)p_xr1, att1, b1,
                        (const float*)p_ee1, (const float*)p_attW1, (float*)p_h);
    k_smaggr_full<<<D1/32, 512>>>((const float*)p_h, (float*)p_fx);

    // xl2/xr2 (shared across all args)
    {
        dim3 g(D1/64, (Nn+127)/128);
        k_gemm_tf32<<<g, 256>>>((float*)p_xl2, (const float*)p_h, Wl2, Nn, D1, D1);
        k_gemm_tf32<<<g, 256>>>((float*)p_xr2, (const float*)p_h, Wr2, Nn, D1, D1);
    }

    // per-arg kept-edge attr counts -> self-loop terms
    k_cntkept<<<128, 256>>>(srcA, dstA, edge_attr, (const unsigned*)p_mB);
    k_eeloop2k<<<Aa, 512>>>();

    // fused 8-arg masked GAT + per-arg softmax aggregation
    k_gat8<<<Nn, 128>>>((const float*)p_xl2, (const float*)p_xr2, att2, b2,
                        (const float*)p_ee2, (const float*)p_attW2,
                        (float*)p_hiA, (const unsigned*)p_mB);
    {
        dim3 g(D1/32, Aa);
        k_smaggr8<<<g, 512>>>((const float*)p_hiA, (const unsigned*)p_mB, (float*)p_rx);
    }

    // HGT + heads
    k_head<<<1, 512>>>(kqv_f, kqvb_f, kqv_r, kqvb_r, a_rel, m_rel, p_rel,
                       aW_f, ab_f, aW_r, ab_r);
    k_frame<<<1, 512>>>(Wfr, bfr, outp);
    k_roles<<<1, 512>>>(Wro, bro, outp + NFc);
}